// round 5
// baseline (speedup 1.0000x reference)
#include <cuda_runtime.h>

#define S_LEN 4096
#define NB    4
#define DIN   512
#define DOUT  64

// Scratch for projected Q, K, V: [B*S, 64] each (4 MB each). __device__ globals
// are the sanctioned scratch mechanism (no cudaMalloc allowed).
__device__ float g_Q[NB * S_LEN * DOUT];
__device__ float g_K[NB * S_LEN * DOUT];
__device__ float g_V[NB * S_LEN * DOUT];

#define NEG_INF (-1e30f)

// ---------------------------------------------------------------------------
// Projection: Y = X @ W for (Q,K,V).  X: [16384, 512], W: [512, 64].
// Block = 256 threads computes a 64x64 output tile (full output width),
// K staged in chunks of 32. Per-thread 4x4 register tile. ~FFMA roofline.
// ---------------------------------------------------------------------------
__global__ __launch_bounds__(256) void proj_kernel(
    const float* __restrict__ Xk, const float* __restrict__ Xv,
    const float* __restrict__ Xq, const float* __restrict__ Wq,
    const float* __restrict__ Wk, const float* __restrict__ Wv)
{
    __shared__ float Xs[32][68];   // [k][row]  (transposed; pad vs store conflicts)
    __shared__ float Ws[32][68];   // [k][e]

    const float* __restrict__ X;
    const float* __restrict__ W;
    float* __restrict__ Y;
    if (blockIdx.y == 0)      { X = Xq; W = Wq; Y = g_Q; }
    else if (blockIdx.y == 1) { X = Xk; W = Wk; Y = g_K; }
    else                      { X = Xv; W = Wv; Y = g_V; }

    const int tid  = threadIdx.x;
    const int tr   = tid >> 4;       // 0..15  -> rows tr*4..tr*4+3
    const int tc   = tid & 15;       // 0..15  -> cols tc*4..tc*4+3
    const int row0 = blockIdx.x * 64;

    float acc[4][4];
#pragma unroll
    for (int i = 0; i < 4; ++i)
#pragma unroll
        for (int j = 0; j < 4; ++j) acc[i][j] = 0.0f;

#pragma unroll 1
    for (int k0 = 0; k0 < DIN; k0 += 32) {
        // Load X tile (64 rows x 32 k), store transposed: Xs[k][row]
#pragma unroll
        for (int it = 0; it < 2; ++it) {
            int idx = tid + it * 256;            // 0..511
            int r   = idx >> 3;                  // 0..63
            int kk  = (idx & 7) << 2;            // 0,4,...,28
            float4 v = *(const float4*)(X + (size_t)(row0 + r) * DIN + k0 + kk);
            Xs[kk + 0][r] = v.x;
            Xs[kk + 1][r] = v.y;
            Xs[kk + 2][r] = v.z;
            Xs[kk + 3][r] = v.w;
        }
        // Load W tile (32 k x 64 e), natural layout
#pragma unroll
        for (int it = 0; it < 2; ++it) {
            int idx = tid + it * 256;
            int kk  = idx >> 4;                  // 0..31
            int e   = (idx & 15) << 2;           // 0..60
            *(float4*)(&Ws[kk][e]) =
                *(const float4*)(W + (size_t)(k0 + kk) * DOUT + e);
        }
        __syncthreads();

#pragma unroll
        for (int k = 0; k < 32; ++k) {
            float4 a4 = *(const float4*)(&Xs[k][tr << 2]);
            float4 b4 = *(const float4*)(&Ws[k][tc << 2]);
            float ar[4] = {a4.x, a4.y, a4.z, a4.w};
            float br[4] = {b4.x, b4.y, b4.z, b4.w};
#pragma unroll
            for (int i = 0; i < 4; ++i)
#pragma unroll
                for (int j = 0; j < 4; ++j)
                    acc[i][j] = fmaf(ar[i], br[j], acc[i][j]);
        }
        __syncthreads();
    }

#pragma unroll
    for (int i = 0; i < 4; ++i) {
        float4 o = make_float4(acc[i][0], acc[i][1], acc[i][2], acc[i][3]);
        *(float4*)(Y + (size_t)(row0 + (tr << 2) + i) * DOUT + (tc << 2)) = o;
    }
}

// ---------------------------------------------------------------------------
// Flash attention, fp32, causal. Block = 512 threads = TWO independent
// 256-thread halves, each owning one 64-row query tile of the (z, 63-z) pair,
// running CONCURRENTLY in disjoint 48KB smem regions. Named barriers
// (bar.sync 1,256 / bar.sync 2,256) keep the halves from stalling each other.
// Every block does exactly 65 kv-tile iterations total; 16 warps/SM.
// ---------------------------------------------------------------------------
__global__ __launch_bounds__(512) void attn_kernel(float* __restrict__ out)
{
    extern __shared__ float smem[];     // 2 * 12288 floats = 96 KB

    const int tid  = threadIdx.x;
    const int half = tid >> 8;          // 0 or 1
    const int lt   = tid & 255;         // thread id within half
    const int tr   = lt >> 4;
    const int tc   = lt & 15;
    const int r0   = tr << 2;
    const int c0   = tc << 2;

    float* __restrict__ Qs = smem + half * 12288;   // [d][r]
    float* __restrict__ KP = Qs + 4096;             // K [d][c] then P [c][r]
    float* __restrict__ Vs = Qs + 8192;             // [c][e]

    const int b  = blockIdx.y;
    const int qt = half ? (63 - (int)blockIdx.x) : (int)blockIdx.x;
    const int qbase = qt << 6;
    const int barid = half + 1;

#define BARH() asm volatile("bar.sync %0, 256;" :: "r"(barid) : "memory")

    const float* __restrict__ Qb = g_Q + (size_t)b * S_LEN * DOUT;
    const float* __restrict__ Kb = g_K + (size_t)b * S_LEN * DOUT;
    const float* __restrict__ Vb = g_V + (size_t)b * S_LEN * DOUT;
    float* __restrict__ Ob = out + (size_t)b * S_LEN * DOUT;

    // Load Q tile transposed: Qs[d][r] = Q[qbase+r][d]
#pragma unroll
    for (int it = 0; it < 4; ++it) {
        int idx = lt + it * 256;             // 0..1023
        int r   = idx >> 4;                  // 0..63
        int d0  = (idx & 15) << 2;           // 0..60
        float4 v = *(const float4*)(Qb + (size_t)(qbase + r) * DOUT + d0);
        Qs[(d0 + 0) * 64 + r] = v.x;
        Qs[(d0 + 1) * 64 + r] = v.y;
        Qs[(d0 + 2) * 64 + r] = v.z;
        Qs[(d0 + 3) * 64 + r] = v.w;
    }

    float m[4], l[4], acc[4][4];
#pragma unroll
    for (int i = 0; i < 4; ++i) {
        m[i] = NEG_INF;
        l[i] = 0.0f;
#pragma unroll
        for (int j = 0; j < 4; ++j) acc[i][j] = 0.0f;
    }

#pragma unroll 1
    for (int jt = 0; jt <= qt; ++jt) {
        const int kbase = jt << 6;
        BARH();   // prior PV reads of KP/Vs done (and Q stores on iter 0 ordered below)
        // K transposed into KP [d][c]; V natural into Vs [c][e]
#pragma unroll
        for (int it = 0; it < 4; ++it) {
            int idx = lt + it * 256;
            int c   = idx >> 4;
            int d0  = (idx & 15) << 2;
            float4 kv = *(const float4*)(Kb + (size_t)(kbase + c) * DOUT + d0);
            KP[(d0 + 0) * 64 + c] = kv.x;
            KP[(d0 + 1) * 64 + c] = kv.y;
            KP[(d0 + 2) * 64 + c] = kv.z;
            KP[(d0 + 3) * 64 + c] = kv.w;
            *(float4*)(&Vs[c * 64 + d0]) =
                *(const float4*)(Vb + (size_t)(kbase + c) * DOUT + d0);
        }
        BARH();   // Q + K + V stores visible

        // ---- S = Q K^T ----
        float s[4][4];
#pragma unroll
        for (int i = 0; i < 4; ++i)
#pragma unroll
            for (int j = 0; j < 4; ++j) s[i][j] = 0.0f;

#pragma unroll 16
        for (int d = 0; d < 64; ++d) {
            float4 a4 = *(const float4*)(&Qs[d * 64 + r0]);
            float4 b4 = *(const float4*)(&KP[d * 64 + c0]);
            float ar[4] = {a4.x, a4.y, a4.z, a4.w};
            float br[4] = {b4.x, b4.y, b4.z, b4.w};
#pragma unroll
            for (int i = 0; i < 4; ++i)
#pragma unroll
                for (int j = 0; j < 4; ++j)
                    s[i][j] = fmaf(ar[i], br[j], s[i][j]);
        }

        // scale + causal mask (only diagonal tile needs masking)
        if (jt == qt) {
#pragma unroll
            for (int i = 0; i < 4; ++i)
#pragma unroll
                for (int j = 0; j < 4; ++j)
                    s[i][j] = (c0 + j <= r0 + i) ? s[i][j] * 0.125f : NEG_INF;
        } else {
#pragma unroll
            for (int i = 0; i < 4; ++i)
#pragma unroll
                for (int j = 0; j < 4; ++j)
                    s[i][j] *= 0.125f;
        }

        BARH();   // everyone in this half done reading K before P overwrites KP

        // ---- online softmax + write P [c][r] ----
#pragma unroll
        for (int i = 0; i < 4; ++i) {
            float tm = fmaxf(fmaxf(s[i][0], s[i][1]), fmaxf(s[i][2], s[i][3]));
            tm = fmaxf(tm, __shfl_xor_sync(0xffffffffu, tm, 1));
            tm = fmaxf(tm, __shfl_xor_sync(0xffffffffu, tm, 2));
            tm = fmaxf(tm, __shfl_xor_sync(0xffffffffu, tm, 4));
            tm = fmaxf(tm, __shfl_xor_sync(0xffffffffu, tm, 8));
            float mn   = fmaxf(m[i], tm);
            float corr = __expf(m[i] - mn);
            float p0 = __expf(s[i][0] - mn);
            float p1 = __expf(s[i][1] - mn);
            float p2 = __expf(s[i][2] - mn);
            float p3 = __expf(s[i][3] - mn);
            float ps = (p0 + p1) + (p2 + p3);
            ps += __shfl_xor_sync(0xffffffffu, ps, 1);
            ps += __shfl_xor_sync(0xffffffffu, ps, 2);
            ps += __shfl_xor_sync(0xffffffffu, ps, 4);
            ps += __shfl_xor_sync(0xffffffffu, ps, 8);
            l[i] = l[i] * corr + ps;
            m[i] = mn;
            acc[i][0] *= corr;
            acc[i][1] *= corr;
            acc[i][2] *= corr;
            acc[i][3] *= corr;
            KP[(c0 + 0) * 64 + r0 + i] = p0;
            KP[(c0 + 1) * 64 + r0 + i] = p1;
            KP[(c0 + 2) * 64 + r0 + i] = p2;
            KP[(c0 + 3) * 64 + r0 + i] = p3;
        }
        BARH();   // P stores visible

        // ---- O += P V ----
#pragma unroll 16
        for (int c = 0; c < 64; ++c) {
            float4 a4 = *(const float4*)(&KP[c * 64 + r0]);
            float4 v4 = *(const float4*)(&Vs[c * 64 + c0]);
            float ar[4] = {a4.x, a4.y, a4.z, a4.w};
            float vr[4] = {v4.x, v4.y, v4.z, v4.w};
#pragma unroll
            for (int i = 0; i < 4; ++i)
#pragma unroll
                for (int j = 0; j < 4; ++j)
                    acc[i][j] = fmaf(ar[i], vr[j], acc[i][j]);
        }
    }

    // ---- finalize: Z = acc / l ----
#pragma unroll
    for (int i = 0; i < 4; ++i) {
        float inv = __fdividef(1.0f, l[i]);
        float4 o = make_float4(acc[i][0] * inv, acc[i][1] * inv,
                               acc[i][2] * inv, acc[i][3] * inv);
        *(float4*)(Ob + (size_t)(qbase + r0 + i) * DOUT + c0) = o;
    }
#undef BARH
}

extern "C" void kernel_launch(void* const* d_in, const int* in_sizes, int n_in,
                              void* d_out, int out_size)
{
    (void)in_sizes; (void)n_in; (void)out_size;
    const float* key_in   = (const float*)d_in[0];
    const float* value_in = (const float*)d_in[1];
    const float* query_in = (const float*)d_in[2];
    const float* Wq       = (const float*)d_in[3];
    const float* Wk       = (const float*)d_in[4];
    const float* Wv       = (const float*)d_in[5];
    float* out = (float*)d_out;

    dim3 pgrid(NB * S_LEN / 64, 3);   // (256, 3)
    proj_kernel<<<pgrid, 256>>>(key_in, value_in, query_in, Wq, Wk, Wv);

    // 96KB dynamic smem for the two concurrent tile-halves.
    static int smem_set = 0;
    if (!smem_set) {
        cudaFuncSetAttribute(attn_kernel,
                             cudaFuncAttributeMaxDynamicSharedMemorySize,
                             2 * 12288 * sizeof(float));
        smem_set = 1;
    }
    dim3 agrid((S_LEN / 64) / 2, NB); // (32, 4): paired q-tiles in one 512-thr block
    attn_kernel<<<agrid, 512, 2 * 12288 * sizeof(float)>>>(out);
}

// round 7
// speedup vs baseline: 2.2664x; 2.2664x over previous
#include <cuda_runtime.h>
#include <cuda_bf16.h>
#include <cstdint>

#define S_LEN 4096
#define NB    4
#define DIN   512
#define DOUT  64

// Scratch (device globals = sanctioned scratch; no cudaMalloc allowed)
__device__ float g_Q[NB * S_LEN * DOUT];
__device__ float g_K[NB * S_LEN * DOUT];
__device__ float g_V[NB * S_LEN * DOUT];
// Partial outputs: [b*32+t][part(2)][row(128)][e(64)], and l: [...][row]
__device__ float g_Opart[NB * 32 * 2 * 128 * 64];
__device__ float g_lpart[NB * 32 * 2 * 128];

// ---------------------------------------------------------------------------
// helpers
// ---------------------------------------------------------------------------
__device__ __forceinline__ float ex2(float x) {
    float r; asm("ex2.approx.f32 %0, %1;" : "=f"(r) : "f"(x)); return r;
}
// bf16 hi/lo split of two floats -> packed bf16x2 (low half = first arg)
__device__ __forceinline__ void split2(float a, float b, uint32_t& hi, uint32_t& lo) {
    __nv_bfloat16 ah = __float2bfloat16(a), bh = __float2bfloat16(b);
    __nv_bfloat16 al = __float2bfloat16(a - __bfloat162float(ah));
    __nv_bfloat16 bl = __float2bfloat16(b - __bfloat162float(bh));
    hi = (uint32_t)__bfloat16_as_ushort(ah) | ((uint32_t)__bfloat16_as_ushort(bh) << 16);
    lo = (uint32_t)__bfloat16_as_ushort(al) | ((uint32_t)__bfloat16_as_ushort(bl) << 16);
}

// D += A*B  (m16n8k16, bf16 in, f32 accum)
#define MMA(d, a, b0, b1)                                                    \
    asm volatile("mma.sync.aligned.m16n8k16.row.col.f32.bf16.bf16.f32 "      \
        "{%0,%1,%2,%3}, {%4,%5,%6,%7}, {%8,%9}, {%0,%1,%2,%3};"              \
        : "+f"((d)[0]), "+f"((d)[1]), "+f"((d)[2]), "+f"((d)[3])             \
        : "r"((a)[0]), "r"((a)[1]), "r"((a)[2]), "r"((a)[3]),                \
          "r"(b0), "r"(b1))

// smem layout (u32 indices). Row stride 36 u32 => B-frag loads conflict-free.
#define RS      36
#define QH_OFF  0
#define QL_OFF  (128 * RS)
#define KH_OFF  (2 * 128 * RS)
#define KL_OFF  (KH_OFF + 64 * RS)
#define VH_OFF  (KH_OFF + 2 * 64 * RS)
#define VL_OFF  (KH_OFF + 3 * 64 * RS)
#define SMEM_U32 (KH_OFF + 4 * 64 * RS)

// Q scale: 1/sqrt(64) * log2(e)  (softmax done in base-2)
#define QSCALE 0.18033688011112042f

// ---------------------------------------------------------------------------
// Projection (scalar, ~FFMA roofline): Y = X @ W for (Q,K,V).
// ---------------------------------------------------------------------------
__global__ __launch_bounds__(256) void proj_kernel(
    const float* __restrict__ Xk, const float* __restrict__ Xv,
    const float* __restrict__ Xq, const float* __restrict__ Wq,
    const float* __restrict__ Wk, const float* __restrict__ Wv)
{
    __shared__ float Xs[32][68];
    __shared__ float Ws[32][68];

    const float* __restrict__ X;
    const float* __restrict__ W;
    float* __restrict__ Y;
    if (blockIdx.y == 0)      { X = Xq; W = Wq; Y = g_Q; }
    else if (blockIdx.y == 1) { X = Xk; W = Wk; Y = g_K; }
    else                      { X = Xv; W = Wv; Y = g_V; }

    const int tid  = threadIdx.x;
    const int tr   = tid >> 4;
    const int tc   = tid & 15;
    const int row0 = blockIdx.x * 64;

    float acc[4][4];
#pragma unroll
    for (int i = 0; i < 4; ++i)
#pragma unroll
        for (int j = 0; j < 4; ++j) acc[i][j] = 0.0f;

#pragma unroll 1
    for (int k0 = 0; k0 < DIN; k0 += 32) {
#pragma unroll
        for (int it = 0; it < 2; ++it) {
            int idx = tid + it * 256;
            int r   = idx >> 3;
            int kk  = (idx & 7) << 2;
            float4 v = *(const float4*)(X + (size_t)(row0 + r) * DIN + k0 + kk);
            Xs[kk + 0][r] = v.x; Xs[kk + 1][r] = v.y;
            Xs[kk + 2][r] = v.z; Xs[kk + 3][r] = v.w;
        }
#pragma unroll
        for (int it = 0; it < 2; ++it) {
            int idx = tid + it * 256;
            int kk  = idx >> 4;
            int e   = (idx & 15) << 2;
            *(float4*)(&Ws[kk][e]) = *(const float4*)(W + (size_t)(k0 + kk) * DOUT + e);
        }
        __syncthreads();
#pragma unroll
        for (int k = 0; k < 32; ++k) {
            float4 a4 = *(const float4*)(&Xs[k][tr << 2]);
            float4 b4 = *(const float4*)(&Ws[k][tc << 2]);
            float ar[4] = {a4.x, a4.y, a4.z, a4.w};
            float br[4] = {b4.x, b4.y, b4.z, b4.w};
#pragma unroll
            for (int i = 0; i < 4; ++i)
#pragma unroll
                for (int j = 0; j < 4; ++j)
                    acc[i][j] = fmaf(ar[i], br[j], acc[i][j]);
        }
        __syncthreads();
    }
#pragma unroll
    for (int i = 0; i < 4; ++i) {
        float4 o = make_float4(acc[i][0], acc[i][1], acc[i][2], acc[i][3]);
        *(float4*)(Y + (size_t)(row0 + (tr << 2) + i) * DOUT + (tc << 2)) = o;
    }
}

// ---------------------------------------------------------------------------
// HMMA flash attention. CTA = 256 threads = 8 warps; q-tile M=128 (16 rows per
// warp), kv-tile N=64. bf16 hi/lo 3-pass split for QK^T and PV. Static-max
// base-2 softmax; O accumulates in f32 mma fragments. Balanced (t,31-t) split:
// CTA sub0 = tile t full + tile 31-t kv[0,32-2t); sub1 = tile 31-t kv rest.
// ---------------------------------------------------------------------------
__global__ __launch_bounds__(256, 1) void attn_kernel()
{
    extern __shared__ uint32_t sm[];
    const int tid  = threadIdx.x;
    const int w    = tid >> 5;
    const int lane = tid & 31;
    const int gq   = lane >> 2;     // group id (row within frag)
    const int tq   = lane & 3;      // thread-in-group (col pairs)
    const int m0   = w * 16;        // warp's 16 q-rows within the 128-row tile

    const int b   = blockIdx.y;
    const int x   = blockIdx.x;     // 0..31
    const int pr  = x >> 1;
    const int sub = x & 1;

    const float* __restrict__ Qg = g_Q + (size_t)b * S_LEN * DOUT;
    const float* __restrict__ Kg = g_K + (size_t)b * S_LEN * DOUT;
    const float* __restrict__ Vg = g_V + (size_t)b * S_LEN * DOUT;

    const int nseg = sub ? 1 : 2;
#pragma unroll 1
    for (int seg = 0; seg < nseg; ++seg) {
        int t, j0, j1, part, diag;
        if (!sub) {
            if (seg == 0) { t = pr;      j0 = 0;           j1 = 2 * pr + 2;  part = 0; diag = 1; }
            else          { t = 31 - pr; j0 = 0;           j1 = 32 - 2 * pr; part = 0; diag = 0; }
        } else            { t = 31 - pr; j0 = 32 - 2 * pr; j1 = 64 - 2 * pr; part = 1; diag = 1; }
        const int jmask = diag ? (j1 - 2) : 0x7fffffff;

        // ---- stage Q tile (scaled, hi/lo split) ----
        const float4* Qt = (const float4*)(Qg + (size_t)t * 128 * DOUT);
#pragma unroll
        for (int s = 0; s < 8; ++s) {
            int idx = tid + s * 256;            // 0..2047
            int r   = idx >> 4;
            int d0  = (idx & 15) << 2;
            float4 f = Qt[idx];
            uint32_t h0, l0, h1, l1;
            split2(f.x * QSCALE, f.y * QSCALE, h0, l0);
            split2(f.z * QSCALE, f.w * QSCALE, h1, l1);
            sm[QH_OFF + r * RS + (d0 >> 1)]     = h0;
            sm[QH_OFF + r * RS + (d0 >> 1) + 1] = h1;
            sm[QL_OFF + r * RS + (d0 >> 1)]     = l0;
            sm[QL_OFF + r * RS + (d0 >> 1) + 1] = l1;
        }
        __syncthreads();

        // ---- load persistent Q fragments ----
        uint32_t aQ[2][4][4];
#pragma unroll
        for (int h = 0; h < 2; ++h) {
            int base = h ? QL_OFF : QH_OFF;
#pragma unroll
            for (int c = 0; c < 4; ++c) {
                aQ[h][c][0] = sm[base + (m0 + gq)     * RS + 8 * c + tq];
                aQ[h][c][1] = sm[base + (m0 + 8 + gq) * RS + 8 * c + tq];
                aQ[h][c][2] = sm[base + (m0 + gq)     * RS + 8 * c + tq + 4];
                aQ[h][c][3] = sm[base + (m0 + 8 + gq) * RS + 8 * c + tq + 4];
            }
        }

        float oacc[8][4];
#pragma unroll
        for (int n = 0; n < 8; ++n)
#pragma unroll
            for (int k = 0; k < 4; ++k) oacc[n][k] = 0.0f;
        float lA = 0.0f, lB = 0.0f;

        const int qrow0 = t * 128 + m0 + gq;    // global q row (frag row 0)
        const int qrow1 = qrow0 + 8;

#pragma unroll 1
        for (int j = j0; j < j1; ++j) {
            const int kb = j << 6;
            __syncthreads();   // previous iter's mma reads of K/V done

            // ---- stage K (hi/lo, [kv][d]) and V^T (hi/lo, [e][kv]) ----
            const float4* Kt = (const float4*)(Kg + (size_t)kb * DOUT);
            const float4* Vt = (const float4*)(Vg + (size_t)kb * DOUT);
#pragma unroll
            for (int s = 0; s < 4; ++s) {
                int idx = tid + s * 256;        // 0..1023
                int c   = idx >> 4;             // kv row
                int d0  = (idx & 15) << 2;
                float4 fk = Kt[idx];
                uint32_t h0, l0, h1, l1;
                split2(fk.x, fk.y, h0, l0);
                split2(fk.z, fk.w, h1, l1);
                sm[KH_OFF + c * RS + (d0 >> 1)]     = h0;
                sm[KH_OFF + c * RS + (d0 >> 1) + 1] = h1;
                sm[KL_OFF + c * RS + (d0 >> 1)]     = l0;
                sm[KL_OFF + c * RS + (d0 >> 1) + 1] = l1;
                float4 fv = Vt[idx];
                float vv[4] = {fv.x, fv.y, fv.z, fv.w};
#pragma unroll
                for (int jj = 0; jj < 4; ++jj) {
                    int e = d0 + jj;
                    __nv_bfloat16 vh = __float2bfloat16(vv[jj]);
                    __nv_bfloat16 vl = __float2bfloat16(vv[jj] - __bfloat162float(vh));
                    ((uint16_t*)&sm[VH_OFF + e * RS + (c >> 1)])[c & 1] = __bfloat16_as_ushort(vh);
                    ((uint16_t*)&sm[VL_OFF + e * RS + (c >> 1)])[c & 1] = __bfloat16_as_ushort(vl);
                }
            }
            __syncthreads();

            // ---- S = Q K^T (3-pass split) ----
            float sacc[8][4];
#pragma unroll
            for (int n = 0; n < 8; ++n)
#pragma unroll
                for (int k = 0; k < 4; ++k) sacc[n][k] = 0.0f;

#pragma unroll
            for (int c = 0; c < 4; ++c) {
#pragma unroll
                for (int n = 0; n < 8; ++n) {
                    int rb = (n * 8 + gq) * RS + 8 * c + tq;
                    uint32_t bh0 = sm[KH_OFF + rb], bh1 = sm[KH_OFF + rb + 4];
                    MMA(sacc[n], aQ[0][c], bh0, bh1);   // Qh*Kh
                    MMA(sacc[n], aQ[1][c], bh0, bh1);   // Ql*Kh
                    uint32_t bl0 = sm[KL_OFF + rb], bl1 = sm[KL_OFF + rb + 4];
                    MMA(sacc[n], aQ[0][c], bl0, bl1);   // Qh*Kl
                }
            }

            // ---- P = exp2(S) with causal mask; accumulate l ----
            const bool dm = (j >= jmask);
#pragma unroll
            for (int n = 0; n < 8; ++n) {
                int col0 = kb + n * 8 + 2 * tq;
                float e0 = ex2(sacc[n][0]);
                float e1 = ex2(sacc[n][1]);
                float e2 = ex2(sacc[n][2]);
                float e3 = ex2(sacc[n][3]);
                if (dm) {
                    e0 = (col0     <= qrow0) ? e0 : 0.0f;
                    e1 = (col0 + 1 <= qrow0) ? e1 : 0.0f;
                    e2 = (col0     <= qrow1) ? e2 : 0.0f;
                    e3 = (col0 + 1 <= qrow1) ? e3 : 0.0f;
                }
                lA += e0 + e1;
                lB += e2 + e3;
                sacc[n][0] = e0; sacc[n][1] = e1;
                sacc[n][2] = e2; sacc[n][3] = e3;
            }

            // ---- P fragments (hi/lo) straight from S fragments ----
            uint32_t aP[2][4][4];
#pragma unroll
            for (int c = 0; c < 4; ++c) {
                split2(sacc[2 * c][0],     sacc[2 * c][1],     aP[0][c][0], aP[1][c][0]);
                split2(sacc[2 * c][2],     sacc[2 * c][3],     aP[0][c][1], aP[1][c][1]);
                split2(sacc[2 * c + 1][0], sacc[2 * c + 1][1], aP[0][c][2], aP[1][c][2]);
                split2(sacc[2 * c + 1][2], sacc[2 * c + 1][3], aP[0][c][3], aP[1][c][3]);
            }

            // ---- O += P V (3-pass split) ----
#pragma unroll
            for (int c = 0; c < 4; ++c) {
#pragma unroll
                for (int n = 0; n < 8; ++n) {
                    int rb = (n * 8 + gq) * RS + 8 * c + tq;
                    uint32_t bh0 = sm[VH_OFF + rb], bh1 = sm[VH_OFF + rb + 4];
                    MMA(oacc[n], aP[0][c], bh0, bh1);   // Ph*Vh
                    MMA(oacc[n], aP[1][c], bh0, bh1);   // Pl*Vh
                    uint32_t bl0 = sm[VL_OFF + rb], bl1 = sm[VL_OFF + rb + 4];
                    MMA(oacc[n], aP[0][c], bl0, bl1);   // Ph*Vl
                }
            }
        }

        // ---- epilogue: write partial O (unnormalized) + l ----
        lA += __shfl_xor_sync(0xffffffffu, lA, 1);
        lA += __shfl_xor_sync(0xffffffffu, lA, 2);
        lB += __shfl_xor_sync(0xffffffffu, lB, 1);
        lB += __shfl_xor_sync(0xffffffffu, lB, 2);

        const int slot = (b * 32 + t) * 2 + part;
        if (tq == 0) {
            g_lpart[(size_t)slot * 128 + m0 + gq]     = lA;
            g_lpart[(size_t)slot * 128 + m0 + 8 + gq] = lB;
        }
        float* Od = g_Opart + (size_t)slot * 128 * 64;
#pragma unroll
        for (int n = 0; n < 8; ++n) {
            int e = n * 8 + 2 * tq;
            *(float2*)(Od + (size_t)(m0 + gq)     * 64 + e) = make_float2(oacc[n][0], oacc[n][1]);
            *(float2*)(Od + (size_t)(m0 + 8 + gq) * 64 + e) = make_float2(oacc[n][2], oacc[n][3]);
        }
        __syncthreads();   // before next seg rewrites Qs
    }
}

// ---------------------------------------------------------------------------
// Combine: out = (O0 [+ O1]) / (l0 [+ l1]); tiles 0..15 one part, 16..31 two.
// ---------------------------------------------------------------------------
__global__ __launch_bounds__(128) void combine_kernel(float* __restrict__ out)
{
    const int bt = blockIdx.x;        // b*32 + t
    const int t  = bt & 31;
    const int r  = threadIdx.x;
    const float* O0 = g_Opart + (((size_t)bt * 2 + 0) * 128 + r) * 64;
    float l = g_lpart[((size_t)bt * 2 + 0) * 128 + r];
    float* o = out + ((size_t)bt * 128 + r) * 64;

    if (t < 16) {
        float inv = __fdividef(1.0f, l);
#pragma unroll
        for (int k = 0; k < 16; ++k) {
            float4 v = *(const float4*)(O0 + 4 * k);
            v.x *= inv; v.y *= inv; v.z *= inv; v.w *= inv;
            *(float4*)(o + 4 * k) = v;
        }
    } else {
        const float* O1 = g_Opart + (((size_t)bt * 2 + 1) * 128 + r) * 64;
        float inv = __fdividef(1.0f, l + g_lpart[((size_t)bt * 2 + 1) * 128 + r]);
#pragma unroll
        for (int k = 0; k < 16; ++k) {
            float4 a = *(const float4*)(O0 + 4 * k);
            float4 c = *(const float4*)(O1 + 4 * k);
            float4 v = make_float4((a.x + c.x) * inv, (a.y + c.y) * inv,
                                   (a.z + c.z) * inv, (a.w + c.w) * inv);
            *(float4*)(o + 4 * k) = v;
        }
    }
}

extern "C" void kernel_launch(void* const* d_in, const int* in_sizes, int n_in,
                              void* d_out, int out_size)
{
    (void)in_sizes; (void)n_in; (void)out_size;
    const float* key_in   = (const float*)d_in[0];
    const float* value_in = (const float*)d_in[1];
    const float* query_in = (const float*)d_in[2];
    const float* Wq       = (const float*)d_in[3];
    const float* Wk       = (const float*)d_in[4];
    const float* Wv       = (const float*)d_in[5];
    float* out = (float*)d_out;

    static int inited = 0;
    if (!inited) {
        cudaFuncSetAttribute(attn_kernel,
                             cudaFuncAttributeMaxDynamicSharedMemorySize,
                             SMEM_U32 * sizeof(uint32_t));
        inited = 1;
    }

    dim3 pgrid(NB * S_LEN / 64, 3);
    proj_kernel<<<pgrid, 256>>>(key_in, value_in, query_in, Wq, Wk, Wv);

    dim3 agrid(32, NB);               // 128 balanced CTAs
    attn_kernel<<<agrid, 256, SMEM_U32 * sizeof(uint32_t)>>>();

    combine_kernel<<<NB * 32, 128>>>(out);
}

// round 8
// speedup vs baseline: 2.9645x; 1.3080x over previous
#include <cuda_runtime.h>
#include <cuda_bf16.h>
#include <cstdint>

#define S_LEN 4096
#define NB    4
#define DIN   512
#define DOUT  64

// Scratch (device globals = sanctioned scratch; no cudaMalloc allowed)
// Q/K packed bf16 hi/lo pairs along d: [b*S + s][32 u32-pairs]
__device__ uint32_t g_Qh[NB * S_LEN * 32];
__device__ uint32_t g_Ql[NB * S_LEN * 32];
__device__ uint32_t g_Kh[NB * S_LEN * 32];
__device__ uint32_t g_Kl[NB * S_LEN * 32];
// V transposed, pairs along s: [b*64 + e][2048 u32-pairs]
__device__ uint32_t g_Vh[NB * 64 * 2048];
__device__ uint32_t g_Vl[NB * 64 * 2048];
// Partial outputs: [b*32+t][part(2)][row(128)][e(64)], and l: [...][row]
__device__ float g_Opart[NB * 32 * 2 * 128 * 64];
__device__ float g_lpart[NB * 32 * 2 * 128];

// ---------------------------------------------------------------------------
// helpers
// ---------------------------------------------------------------------------
__device__ __forceinline__ float ex2(float x) {
    float r; asm("ex2.approx.f32 %0, %1;" : "=f"(r) : "f"(x)); return r;
}
// bf16 hi/lo split of two floats -> packed bf16x2 (low half = first arg)
__device__ __forceinline__ void split2(float a, float b, uint32_t& hi, uint32_t& lo) {
    __nv_bfloat16 ah = __float2bfloat16(a), bh = __float2bfloat16(b);
    __nv_bfloat16 al = __float2bfloat16(a - __bfloat162float(ah));
    __nv_bfloat16 bl = __float2bfloat16(b - __bfloat162float(bh));
    hi = (uint32_t)__bfloat16_as_ushort(ah) | ((uint32_t)__bfloat16_as_ushort(bh) << 16);
    lo = (uint32_t)__bfloat16_as_ushort(al) | ((uint32_t)__bfloat16_as_ushort(bl) << 16);
}

// D += A*B  (m16n8k16, bf16 in, f32 accum)
#define MMA(d, a, b0, b1)                                                    \
    asm volatile("mma.sync.aligned.m16n8k16.row.col.f32.bf16.bf16.f32 "      \
        "{%0,%1,%2,%3}, {%4,%5,%6,%7}, {%8,%9}, {%0,%1,%2,%3};"              \
        : "+f"((d)[0]), "+f"((d)[1]), "+f"((d)[2]), "+f"((d)[3])             \
        : "r"((a)[0]), "r"((a)[1]), "r"((a)[2]), "r"((a)[3]),                \
          "r"(b0), "r"(b1))

// Q scale: 1/sqrt(64) * log2(e)  (softmax done in base-2)
#define QSCALE 0.18033688011112042f

// ===========================================================================
// Tensorized projection: Y = X @ W (bf16 hi/lo, 3-pass). CTA = 256 thr,
// 128-row output tile, K staged in chunks of 64. Outputs written as packed
// bf16 hi/lo (Q pre-scaled; V transposed [e][s]).
// ===========================================================================
#define PRS 36
#define XH_OFF 0
#define XL_OFF (128 * PRS)
#define WH_OFF (2 * 128 * PRS)
#define WL_OFF (WH_OFF + 64 * PRS)
#define PSM_U32 (WH_OFF + 2 * 64 * PRS)

__global__ __launch_bounds__(256, 1) void proj_kernel(
    const float* __restrict__ Xk, const float* __restrict__ Xv,
    const float* __restrict__ Xq, const float* __restrict__ Wq,
    const float* __restrict__ Wk, const float* __restrict__ Wv)
{
    extern __shared__ uint32_t sm[];
    const int tid  = threadIdx.x;
    const int w    = tid >> 5;
    const int lane = tid & 31;
    const int gq   = lane >> 2;
    const int tq   = lane & 3;
    const int m0   = w * 16;
    const int t    = blockIdx.x;        // 0..127 (row tile over all batches)
    const int mat  = blockIdx.y;        // 0=Q 1=K 2=V

    const float* __restrict__ X = (mat == 0) ? Xq : (mat == 1) ? Xk : Xv;
    const float* __restrict__ W = (mat == 0) ? Wq : (mat == 1) ? Wk : Wv;

    float oacc[8][4];
#pragma unroll
    for (int n = 0; n < 8; ++n)
#pragma unroll
        for (int k = 0; k < 4; ++k) oacc[n][k] = 0.0f;

#pragma unroll 1
    for (int k0 = 0; k0 < DIN; k0 += 64) {
        if (k0) __syncthreads();
        // stage X tile [128][64] hi/lo (pairs along k)
#pragma unroll
        for (int s = 0; s < 8; ++s) {
            int idx = tid + s * 256;            // 0..2047
            int r   = idx >> 4;
            int d0  = (idx & 15) << 2;
            float4 f = *(const float4*)(X + (size_t)(t * 128 + r) * DIN + k0 + d0);
            uint32_t h0, l0, h1, l1;
            split2(f.x, f.y, h0, l0);
            split2(f.z, f.w, h1, l1);
            sm[XH_OFF + r * PRS + (d0 >> 1)]     = h0;
            sm[XH_OFF + r * PRS + (d0 >> 1) + 1] = h1;
            sm[XL_OFF + r * PRS + (d0 >> 1)]     = l0;
            sm[XL_OFF + r * PRS + (d0 >> 1) + 1] = l1;
        }
        // stage W^T tile [e][64k] hi/lo (pairs along k)
#pragma unroll
        for (int s = 0; s < 4; ++s) {
            int idx = tid + s * 256;            // 0..1023
            int k   = idx >> 4;
            int e0  = (idx & 15) << 2;
            float4 f = *(const float4*)(W + (size_t)(k0 + k) * DOUT + e0);
            float vv[4] = {f.x, f.y, f.z, f.w};
#pragma unroll
            for (int jj = 0; jj < 4; ++jj) {
                int e = e0 + jj;
                __nv_bfloat16 vh = __float2bfloat16(vv[jj]);
                __nv_bfloat16 vl = __float2bfloat16(vv[jj] - __bfloat162float(vh));
                ((uint16_t*)&sm[WH_OFF + e * PRS + (k >> 1)])[k & 1] = __bfloat16_as_ushort(vh);
                ((uint16_t*)&sm[WL_OFF + e * PRS + (k >> 1)])[k & 1] = __bfloat16_as_ushort(vl);
            }
        }
        __syncthreads();

        // A fragments (X hi/lo)
        uint32_t aX[2][4][4];
#pragma unroll
        for (int h = 0; h < 2; ++h) {
            int base = h ? XL_OFF : XH_OFF;
#pragma unroll
            for (int c = 0; c < 4; ++c) {
                aX[h][c][0] = sm[base + (m0 + gq)     * PRS + 8 * c + tq];
                aX[h][c][1] = sm[base + (m0 + 8 + gq) * PRS + 8 * c + tq];
                aX[h][c][2] = sm[base + (m0 + gq)     * PRS + 8 * c + tq + 4];
                aX[h][c][3] = sm[base + (m0 + 8 + gq) * PRS + 8 * c + tq + 4];
            }
        }
        // Y += X W (3-pass)
#pragma unroll
        for (int c = 0; c < 4; ++c) {
#pragma unroll
            for (int n = 0; n < 8; ++n) {
                int rb = (n * 8 + gq) * PRS + 8 * c + tq;
                uint32_t bh0 = sm[WH_OFF + rb], bh1 = sm[WH_OFF + rb + 4];
                MMA(oacc[n], aX[0][c], bh0, bh1);
                MMA(oacc[n], aX[1][c], bh0, bh1);
                uint32_t bl0 = sm[WL_OFF + rb], bl1 = sm[WL_OFF + rb + 4];
                MMA(oacc[n], aX[0][c], bl0, bl1);
            }
        }
    }

    // ---- epilogue: write packed bf16 hi/lo ----
    if (mat != 2) {
        uint32_t* Yh = mat ? g_Kh : g_Qh;
        uint32_t* Yl = mat ? g_Kl : g_Ql;
        const float qs = mat ? 1.0f : QSCALE;
        const int row0 = t * 128 + m0 + gq;
#pragma unroll
        for (int n = 0; n < 8; ++n) {
            uint32_t h, l;
            size_t i0 = (size_t)row0 * 32 + n * 4 + tq;
            split2(oacc[n][0] * qs, oacc[n][1] * qs, h, l);
            Yh[i0] = h; Yl[i0] = l;
            size_t i1 = (size_t)(row0 + 8) * 32 + n * 4 + tq;
            split2(oacc[n][2] * qs, oacc[n][3] * qs, h, l);
            Yh[i1] = h; Yl[i1] = l;
        }
    } else {
        uint16_t* Vh16 = (uint16_t*)g_Vh;
        uint16_t* Vl16 = (uint16_t*)g_Vl;
        const int bb = t >> 5;
        const int s0 = (t & 31) * 128 + m0 + gq;
#pragma unroll
        for (int n = 0; n < 8; ++n) {
            int e0 = n * 8 + 2 * tq;
#pragma unroll
            for (int k = 0; k < 4; ++k) {
                int e = e0 + (k & 1);
                int s = s0 + (k >> 1) * 8;
                float v = oacc[n][k];
                __nv_bfloat16 vh = __float2bfloat16(v);
                __nv_bfloat16 vl = __float2bfloat16(v - __bfloat162float(vh));
                size_t a = (size_t)(bb * 64 + e) * S_LEN + s;
                Vh16[a] = __bfloat16_as_ushort(vh);
                Vl16[a] = __bfloat16_as_ushort(vl);
            }
        }
    }
}

// ===========================================================================
// HMMA flash attention (staging = pure copies from packed bf16 buffers).
// CTA = 256 threads = 8 warps; q-tile M=128, kv-tile N=64. Static-max base-2
// softmax; O accumulates in f32 frags. Balanced (t,31-t) two-CTA split.
// ===========================================================================
#define RS      36
#define QH_OFF  0
#define QL_OFF  (128 * RS)
#define KH_OFF  (2 * 128 * RS)
#define KL_OFF  (KH_OFF + 64 * RS)
#define VH_OFF  (KH_OFF + 2 * 64 * RS)
#define VL_OFF  (KH_OFF + 3 * 64 * RS)
#define SMEM_U32 (KH_OFF + 4 * 64 * RS)

__global__ __launch_bounds__(256, 1) void attn_kernel()
{
    extern __shared__ uint32_t sm[];
    const int tid  = threadIdx.x;
    const int w    = tid >> 5;
    const int lane = tid & 31;
    const int gq   = lane >> 2;
    const int tq   = lane & 3;
    const int m0   = w * 16;

    const int b   = blockIdx.y;
    const int x   = blockIdx.x;     // 0..31
    const int pr  = x >> 1;
    const int sub = x & 1;

    const int nseg = sub ? 1 : 2;
#pragma unroll 1
    for (int seg = 0; seg < nseg; ++seg) {
        int t, j0, j1, part, diag;
        if (!sub) {
            if (seg == 0) { t = pr;      j0 = 0;           j1 = 2 * pr + 2;  part = 0; diag = 1; }
            else          { t = 31 - pr; j0 = 0;           j1 = 32 - 2 * pr; part = 0; diag = 0; }
        } else            { t = 31 - pr; j0 = 32 - 2 * pr; j1 = 64 - 2 * pr; part = 1; diag = 1; }
        const int jmask = diag ? (j1 - 2) : 0x7fffffff;

        // ---- stage Q tile (copy, already scaled+split) ----
        const uint2* Qh2 = (const uint2*)(g_Qh + ((size_t)(b * 32 + t) * 128) * 32);
        const uint2* Ql2 = (const uint2*)(g_Ql + ((size_t)(b * 32 + t) * 128) * 32);
#pragma unroll
        for (int s = 0; s < 8; ++s) {
            int idx = tid + s * 256;            // 0..2047 uint2
            int r   = idx >> 4;
            int p2  = idx & 15;
            *(uint2*)&sm[QH_OFF + r * RS + 2 * p2] = Qh2[idx];
            *(uint2*)&sm[QL_OFF + r * RS + 2 * p2] = Ql2[idx];
        }
        __syncthreads();

        // ---- persistent Q fragments ----
        uint32_t aQ[2][4][4];
#pragma unroll
        for (int h = 0; h < 2; ++h) {
            int base = h ? QL_OFF : QH_OFF;
#pragma unroll
            for (int c = 0; c < 4; ++c) {
                aQ[h][c][0] = sm[base + (m0 + gq)     * RS + 8 * c + tq];
                aQ[h][c][1] = sm[base + (m0 + 8 + gq) * RS + 8 * c + tq];
                aQ[h][c][2] = sm[base + (m0 + gq)     * RS + 8 * c + tq + 4];
                aQ[h][c][3] = sm[base + (m0 + 8 + gq) * RS + 8 * c + tq + 4];
            }
        }

        float oacc[8][4];
#pragma unroll
        for (int n = 0; n < 8; ++n)
#pragma unroll
            for (int k = 0; k < 4; ++k) oacc[n][k] = 0.0f;
        float lA = 0.0f, lB = 0.0f;

        const int qrow0 = t * 128 + m0 + gq;
        const int qrow1 = qrow0 + 8;

#pragma unroll 1
        for (int j = j0; j < j1; ++j) {
            const int kb = j << 6;
            __syncthreads();   // previous iter's mma reads of K/V done

            // ---- stage K [c][d-pairs] and V^T [e][s-pairs] (pure copies) ----
            const uint2* Kh2 = (const uint2*)(g_Kh + ((size_t)b * S_LEN + kb) * 32);
            const uint2* Kl2 = (const uint2*)(g_Kl + ((size_t)b * S_LEN + kb) * 32);
            const uint2* Vh2 = (const uint2*)(g_Vh + (size_t)b * 64 * 2048 + (kb >> 1));
            const uint2* Vl2 = (const uint2*)(g_Vl + (size_t)b * 64 * 2048 + (kb >> 1));
#pragma unroll
            for (int s = 0; s < 4; ++s) {
                int idx = tid + s * 256;        // 0..1023 uint2
                int r   = idx >> 4;             // kv row (K) / e row (V)
                int p2  = idx & 15;
                *(uint2*)&sm[KH_OFF + r * RS + 2 * p2] = Kh2[idx];
                *(uint2*)&sm[KL_OFF + r * RS + 2 * p2] = Kl2[idx];
                *(uint2*)&sm[VH_OFF + r * RS + 2 * p2] = Vh2[r * 1024 + p2];
                *(uint2*)&sm[VL_OFF + r * RS + 2 * p2] = Vl2[r * 1024 + p2];
            }
            __syncthreads();

            // ---- S = Q K^T (3-pass split) ----
            float sacc[8][4];
#pragma unroll
            for (int n = 0; n < 8; ++n)
#pragma unroll
                for (int k = 0; k < 4; ++k) sacc[n][k] = 0.0f;

#pragma unroll
            for (int c = 0; c < 4; ++c) {
#pragma unroll
                for (int n = 0; n < 8; ++n) {
                    int rb = (n * 8 + gq) * RS + 8 * c + tq;
                    uint32_t bh0 = sm[KH_OFF + rb], bh1 = sm[KH_OFF + rb + 4];
                    MMA(sacc[n], aQ[0][c], bh0, bh1);
                    MMA(sacc[n], aQ[1][c], bh0, bh1);
                    uint32_t bl0 = sm[KL_OFF + rb], bl1 = sm[KL_OFF + rb + 4];
                    MMA(sacc[n], aQ[0][c], bl0, bl1);
                }
            }

            // ---- P = exp2(S) with causal mask; accumulate l ----
            const bool dm = (j >= jmask);
#pragma unroll
            for (int n = 0; n < 8; ++n) {
                int col0 = kb + n * 8 + 2 * tq;
                float e0 = ex2(sacc[n][0]);
                float e1 = ex2(sacc[n][1]);
                float e2 = ex2(sacc[n][2]);
                float e3 = ex2(sacc[n][3]);
                if (dm) {
                    e0 = (col0     <= qrow0) ? e0 : 0.0f;
                    e1 = (col0 + 1 <= qrow0) ? e1 : 0.0f;
                    e2 = (col0     <= qrow1) ? e2 : 0.0f;
                    e3 = (col0 + 1 <= qrow1) ? e3 : 0.0f;
                }
                lA += e0 + e1;
                lB += e2 + e3;
                sacc[n][0] = e0; sacc[n][1] = e1;
                sacc[n][2] = e2; sacc[n][3] = e3;
            }

            // ---- P fragments (hi/lo) straight from S fragments ----
            uint32_t aP[2][4][4];
#pragma unroll
            for (int c = 0; c < 4; ++c) {
                split2(sacc[2 * c][0],     sacc[2 * c][1],     aP[0][c][0], aP[1][c][0]);
                split2(sacc[2 * c][2],     sacc[2 * c][3],     aP[0][c][1], aP[1][c][1]);
                split2(sacc[2 * c + 1][0], sacc[2 * c + 1][1], aP[0][c][2], aP[1][c][2]);
                split2(sacc[2 * c + 1][2], sacc[2 * c + 1][3], aP[0][c][3], aP[1][c][3]);
            }

            // ---- O += P V (3-pass split) ----
#pragma unroll
            for (int c = 0; c < 4; ++c) {
#pragma unroll
                for (int n = 0; n < 8; ++n) {
                    int rb = (n * 8 + gq) * RS + 8 * c + tq;
                    uint32_t bh0 = sm[VH_OFF + rb], bh1 = sm[VH_OFF + rb + 4];
                    MMA(oacc[n], aP[0][c], bh0, bh1);
                    MMA(oacc[n], aP[1][c], bh0, bh1);
                    uint32_t bl0 = sm[VL_OFF + rb], bl1 = sm[VL_OFF + rb + 4];
                    MMA(oacc[n], aP[0][c], bl0, bl1);
                }
            }
        }

        // ---- epilogue: write partial O (unnormalized) + l ----
        lA += __shfl_xor_sync(0xffffffffu, lA, 1);
        lA += __shfl_xor_sync(0xffffffffu, lA, 2);
        lB += __shfl_xor_sync(0xffffffffu, lB, 1);
        lB += __shfl_xor_sync(0xffffffffu, lB, 2);

        const int slot = (b * 32 + t) * 2 + part;
        if (tq == 0) {
            g_lpart[(size_t)slot * 128 + m0 + gq]     = lA;
            g_lpart[(size_t)slot * 128 + m0 + 8 + gq] = lB;
        }
        float* Od = g_Opart + (size_t)slot * 128 * 64;
#pragma unroll
        for (int n = 0; n < 8; ++n) {
            int e = n * 8 + 2 * tq;
            *(float2*)(Od + (size_t)(m0 + gq)     * 64 + e) = make_float2(oacc[n][0], oacc[n][1]);
            *(float2*)(Od + (size_t)(m0 + 8 + gq) * 64 + e) = make_float2(oacc[n][2], oacc[n][3]);
        }
        __syncthreads();   // before next seg rewrites Qs
    }
}

// ---------------------------------------------------------------------------
// Combine: out = (O0 [+ O1]) / (l0 [+ l1]); tiles 0..15 one part, 16..31 two.
// ---------------------------------------------------------------------------
__global__ __launch_bounds__(128) void combine_kernel(float* __restrict__ out)
{
    const int bt = blockIdx.x;        // b*32 + t
    const int t  = bt & 31;
    const int r  = threadIdx.x;
    const float* O0 = g_Opart + (((size_t)bt * 2 + 0) * 128 + r) * 64;
    float l = g_lpart[((size_t)bt * 2 + 0) * 128 + r];
    float* o = out + ((size_t)bt * 128 + r) * 64;

    if (t < 16) {
        float inv = __fdividef(1.0f, l);
#pragma unroll
        for (int k = 0; k < 16; ++k) {
            float4 v = *(const float4*)(O0 + 4 * k);
            v.x *= inv; v.y *= inv; v.z *= inv; v.w *= inv;
            *(float4*)(o + 4 * k) = v;
        }
    } else {
        const float* O1 = g_Opart + (((size_t)bt * 2 + 1) * 128 + r) * 64;
        float inv = __fdividef(1.0f, l + g_lpart[((size_t)bt * 2 + 1) * 128 + r]);
#pragma unroll
        for (int k = 0; k < 16; ++k) {
            float4 a = *(const float4*)(O0 + 4 * k);
            float4 c = *(const float4*)(O1 + 4 * k);
            float4 v = make_float4((a.x + c.x) * inv, (a.y + c.y) * inv,
                                   (a.z + c.z) * inv, (a.w + c.w) * inv);
            *(float4*)(o + 4 * k) = v;
        }
    }
}

extern "C" void kernel_launch(void* const* d_in, const int* in_sizes, int n_in,
                              void* d_out, int out_size)
{
    (void)in_sizes; (void)n_in; (void)out_size;
    const float* key_in   = (const float*)d_in[0];
    const float* value_in = (const float*)d_in[1];
    const float* query_in = (const float*)d_in[2];
    const float* Wq       = (const float*)d_in[3];
    const float* Wk       = (const float*)d_in[4];
    const float* Wv       = (const float*)d_in[5];
    float* out = (float*)d_out;

    static int inited = 0;
    if (!inited) {
        cudaFuncSetAttribute(proj_kernel,
                             cudaFuncAttributeMaxDynamicSharedMemorySize,
                             PSM_U32 * sizeof(uint32_t));
        cudaFuncSetAttribute(attn_kernel,
                             cudaFuncAttributeMaxDynamicSharedMemorySize,
                             SMEM_U32 * sizeof(uint32_t));
        inited = 1;
    }

    dim3 pgrid(NB * S_LEN / 128, 3);  // (128, 3)
    proj_kernel<<<pgrid, 256, PSM_U32 * sizeof(uint32_t)>>>(
        key_in, value_in, query_in, Wq, Wk, Wv);

    dim3 agrid(32, NB);               // 128 balanced CTAs
    attn_kernel<<<agrid, 256, SMEM_U32 * sizeof(uint32_t)>>>();

    combine_kernel<<<NB * 32, 128>>>(out);
}

// round 9
// speedup vs baseline: 3.5919x; 1.2116x over previous
#include <cuda_runtime.h>
#include <cuda_bf16.h>
#include <cstdint>

#define S_LEN 4096
#define NB    4
#define DIN   512
#define DOUT  64

// Scratch (device globals = sanctioned scratch; no cudaMalloc allowed)
// Q/K packed bf16 hi/lo pairs along d: [b*S + s][32 u32-pairs]
__device__ uint32_t g_Qh[NB * S_LEN * 32];
__device__ uint32_t g_Ql[NB * S_LEN * 32];
__device__ uint32_t g_Kh[NB * S_LEN * 32];
__device__ uint32_t g_Kl[NB * S_LEN * 32];
// V transposed, pairs along s: [b*64 + e][2048 u32-pairs]
__device__ uint32_t g_Vh[NB * 64 * 2048];
__device__ uint32_t g_Vl[NB * 64 * 2048];
// Pre-split W^T: [mat][e(64)][k-pair(256)]
__device__ uint32_t g_WTh[3 * 64 * 256];
__device__ uint32_t g_WTl[3 * 64 * 256];
// Partial outputs: [b*64+t][part(2)][row(64)][e(64)], and l: [...][row]
__device__ float g_Opart[NB * 64 * 2 * 64 * 64];
__device__ float g_lpart[NB * 64 * 2 * 64];

// ---------------------------------------------------------------------------
// helpers
// ---------------------------------------------------------------------------
__device__ __forceinline__ float ex2(float x) {
    float r; asm("ex2.approx.f32 %0, %1;" : "=f"(r) : "f"(x)); return r;
}
__device__ __forceinline__ void split2(float a, float b, uint32_t& hi, uint32_t& lo) {
    __nv_bfloat16 ah = __float2bfloat16(a), bh = __float2bfloat16(b);
    __nv_bfloat16 al = __float2bfloat16(a - __bfloat162float(ah));
    __nv_bfloat16 bl = __float2bfloat16(b - __bfloat162float(bh));
    hi = (uint32_t)__bfloat16_as_ushort(ah) | ((uint32_t)__bfloat16_as_ushort(bh) << 16);
    lo = (uint32_t)__bfloat16_as_ushort(al) | ((uint32_t)__bfloat16_as_ushort(bl) << 16);
}

// D += A*B  (m16n8k16, bf16 in, f32 accum)
#define MMA(d, a, b0, b1)                                                    \
    asm volatile("mma.sync.aligned.m16n8k16.row.col.f32.bf16.bf16.f32 "      \
        "{%0,%1,%2,%3}, {%4,%5,%6,%7}, {%8,%9}, {%0,%1,%2,%3};"              \
        : "+f"((d)[0]), "+f"((d)[1]), "+f"((d)[2]), "+f"((d)[3])             \
        : "r"((a)[0]), "r"((a)[1]), "r"((a)[2]), "r"((a)[3]),                \
          "r"(b0), "r"(b1))

// Q scale: 1/sqrt(64) * log2(e)
#define QSCALE 0.18033688011112042f

// ===========================================================================
// Prep: split W^T into packed bf16 hi/lo global buffers. One-shot, tiny.
// ===========================================================================
__global__ __launch_bounds__(256) void prep_kernel(
    const float* __restrict__ Wq, const float* __restrict__ Wk,
    const float* __restrict__ Wv)
{
    int idx = blockIdx.x * 256 + threadIdx.x;          // 0..49151
    int mat = idx >> 14;
    int rem = idx & 16383;
    int e   = rem >> 8;
    int p   = rem & 255;
    const float* __restrict__ W = (mat == 0) ? Wq : (mat == 1) ? Wk : Wv;
    float a = W[(2 * p)     * DOUT + e];
    float b = W[(2 * p + 1) * DOUT + e];
    uint32_t h, l;
    split2(a, b, h, l);
    g_WTh[idx] = h;
    g_WTl[idx] = l;
}

// ===========================================================================
// Tensorized projection, 2 CTAs/SM. Y = X @ W (bf16 hi/lo, 3-pass).
// CTA = 256 thr, 128-row tile, K chunks of 64. W staged as pure copies.
// ===========================================================================
#define PRS 36
#define XH_OFF 0
#define XL_OFF (128 * PRS)
#define WH_OFF (2 * 128 * PRS)
#define WL_OFF (WH_OFF + 64 * PRS)
#define PSM_U32 (WH_OFF + 2 * 64 * PRS)

__global__ __launch_bounds__(256, 2) void proj_kernel(
    const float* __restrict__ Xk, const float* __restrict__ Xv,
    const float* __restrict__ Xq)
{
    extern __shared__ uint32_t sm[];
    const int tid  = threadIdx.x;
    const int w    = tid >> 5;
    const int lane = tid & 31;
    const int gq   = lane >> 2;
    const int tq   = lane & 3;
    const int m0   = w * 16;
    const int t    = blockIdx.x;        // 0..127
    const int mat  = blockIdx.y;        // 0=Q 1=K 2=V

    const float* __restrict__ X = (mat == 0) ? Xq : (mat == 1) ? Xk : Xv;

    float oacc[8][4];
#pragma unroll
    for (int n = 0; n < 8; ++n)
#pragma unroll
        for (int k = 0; k < 4; ++k) oacc[n][k] = 0.0f;

    const uint2* WTh2 = (const uint2*)g_WTh;
    const uint2* WTl2 = (const uint2*)g_WTl;

#pragma unroll 1
    for (int c = 0; c < 8; ++c) {
        const int k0 = c * 64;
        if (c) __syncthreads();
        // stage X tile [128][64] hi/lo (pairs along k)
#pragma unroll
        for (int s = 0; s < 8; ++s) {
            int idx = tid + s * 256;            // 0..2047
            int r   = idx >> 4;
            int d0  = (idx & 15) << 2;
            float4 f = *(const float4*)(X + (size_t)(t * 128 + r) * DIN + k0 + d0);
            uint32_t h0, l0, h1, l1;
            split2(f.x, f.y, h0, l0);
            split2(f.z, f.w, h1, l1);
            sm[XH_OFF + r * PRS + (d0 >> 1)]     = h0;
            sm[XH_OFF + r * PRS + (d0 >> 1) + 1] = h1;
            sm[XL_OFF + r * PRS + (d0 >> 1)]     = l0;
            sm[XL_OFF + r * PRS + (d0 >> 1) + 1] = l1;
        }
        // stage W^T tile [64e][32 pairs] (pure uint2 copies)
#pragma unroll
        for (int s = 0; s < 4; ++s) {
            int idx = tid + s * 256;            // 0..1023 uint2
            int e   = idx >> 4;
            int p2  = idx & 15;
            size_t src = (size_t)(mat * 64 + e) * 128 + c * 16 + p2;
            *(uint2*)&sm[WH_OFF + e * PRS + 2 * p2] = WTh2[src];
            *(uint2*)&sm[WL_OFF + e * PRS + 2 * p2] = WTl2[src];
        }
        __syncthreads();

        uint32_t aX[2][4][4];
#pragma unroll
        for (int h = 0; h < 2; ++h) {
            int base = h ? XL_OFF : XH_OFF;
#pragma unroll
            for (int cc = 0; cc < 4; ++cc) {
                aX[h][cc][0] = sm[base + (m0 + gq)     * PRS + 8 * cc + tq];
                aX[h][cc][1] = sm[base + (m0 + 8 + gq) * PRS + 8 * cc + tq];
                aX[h][cc][2] = sm[base + (m0 + gq)     * PRS + 8 * cc + tq + 4];
                aX[h][cc][3] = sm[base + (m0 + 8 + gq) * PRS + 8 * cc + tq + 4];
            }
        }
#pragma unroll
        for (int cc = 0; cc < 4; ++cc) {
#pragma unroll
            for (int n = 0; n < 8; ++n) {
                int rb = (n * 8 + gq) * PRS + 8 * cc + tq;
                uint32_t bh0 = sm[WH_OFF + rb], bh1 = sm[WH_OFF + rb + 4];
                MMA(oacc[n], aX[0][cc], bh0, bh1);
                MMA(oacc[n], aX[1][cc], bh0, bh1);
                uint32_t bl0 = sm[WL_OFF + rb], bl1 = sm[WL_OFF + rb + 4];
                MMA(oacc[n], aX[0][cc], bl0, bl1);
            }
        }
    }

    // ---- epilogue: write packed bf16 hi/lo ----
    if (mat != 2) {
        uint32_t* Yh = mat ? g_Kh : g_Qh;
        uint32_t* Yl = mat ? g_Kl : g_Ql;
        const float qs = mat ? 1.0f : QSCALE;
        const int row0 = t * 128 + m0 + gq;
#pragma unroll
        for (int n = 0; n < 8; ++n) {
            uint32_t h, l;
            size_t i0 = (size_t)row0 * 32 + n * 4 + tq;
            split2(oacc[n][0] * qs, oacc[n][1] * qs, h, l);
            Yh[i0] = h; Yl[i0] = l;
            size_t i1 = (size_t)(row0 + 8) * 32 + n * 4 + tq;
            split2(oacc[n][2] * qs, oacc[n][3] * qs, h, l);
            Yh[i1] = h; Yl[i1] = l;
        }
    } else {
        uint16_t* Vh16 = (uint16_t*)g_Vh;
        uint16_t* Vl16 = (uint16_t*)g_Vl;
        const int bb = t >> 5;
        const int s0 = (t & 31) * 128 + m0 + gq;
#pragma unroll
        for (int n = 0; n < 8; ++n) {
            int e0 = n * 8 + 2 * tq;
#pragma unroll
            for (int k = 0; k < 4; ++k) {
                int e = e0 + (k & 1);
                int s = s0 + (k >> 1) * 8;
                float v = oacc[n][k];
                __nv_bfloat16 vh = __float2bfloat16(v);
                __nv_bfloat16 vl = __float2bfloat16(v - __bfloat162float(vh));
                size_t a = (size_t)(bb * 64 + e) * S_LEN + s;
                Vh16[a] = __bfloat16_as_ushort(vh);
                Vl16[a] = __bfloat16_as_ushort(vl);
            }
        }
    }
}

// ===========================================================================
// HMMA flash attention. CTA = 128 threads = 4 warps; q-tile M=64, kv-tile
// N=64. 256 CTAs -> 2-3 CTAs/SM. Static-max base-2 softmax; O in f32 frags.
// Pair (t, 63-t): sub0 = tile t full (t+1) + tile 63-t kv[0,32-t) => 33 iters;
// sub1 = tile 63-t kv[32-t,64-t) => 32 iters.
// ===========================================================================
#define RS      36
#define QH_OFF  0
#define QL_OFF  (64 * RS)
#define KH_OFF  (2 * 64 * RS)
#define KL_OFF  (KH_OFF + 64 * RS)
#define VH_OFF  (KH_OFF + 2 * 64 * RS)
#define VL_OFF  (KH_OFF + 3 * 64 * RS)
#define SMEM_U32 (KH_OFF + 4 * 64 * RS)

__global__ __launch_bounds__(128, 1) void attn_kernel()
{
    extern __shared__ uint32_t sm[];
    const int tid  = threadIdx.x;
    const int w    = tid >> 5;
    const int lane = tid & 31;
    const int gq   = lane >> 2;
    const int tq   = lane & 3;
    const int m0   = w * 16;

    const int b   = blockIdx.y;
    const int x   = blockIdx.x;     // 0..63
    const int pr  = x >> 1;         // 0..31
    const int sub = x & 1;

    const int nseg = sub ? 1 : 2;
#pragma unroll 1
    for (int seg = 0; seg < nseg; ++seg) {
        int t, j0, j1, part, diag;
        if (!sub) {
            if (seg == 0) { t = pr;      j0 = 0;       j1 = pr + 1;  part = 0; diag = 1; }
            else          { t = 63 - pr; j0 = 0;       j1 = 32 - pr; part = 0; diag = 0; }
        } else            { t = 63 - pr; j0 = 32 - pr; j1 = 64 - pr; part = 1; diag = 1; }
        const int jmask = diag ? (j1 - 1) : 0x7fffffff;

        // ---- stage Q tile (copy, already scaled+split) ----
        const uint2* Qh2 = (const uint2*)(g_Qh + ((size_t)b * S_LEN + t * 64) * 32);
        const uint2* Ql2 = (const uint2*)(g_Ql + ((size_t)b * S_LEN + t * 64) * 32);
#pragma unroll
        for (int s = 0; s < 8; ++s) {
            int idx = tid + s * 128;            // 0..1023 uint2
            int r   = idx >> 4;
            int p2  = idx & 15;
            *(uint2*)&sm[QH_OFF + r * RS + 2 * p2] = Qh2[idx];
            *(uint2*)&sm[QL_OFF + r * RS + 2 * p2] = Ql2[idx];
        }
        __syncthreads();

        // ---- persistent Q fragments ----
        uint32_t aQ[2][4][4];
#pragma unroll
        for (int h = 0; h < 2; ++h) {
            int base = h ? QL_OFF : QH_OFF;
#pragma unroll
            for (int c = 0; c < 4; ++c) {
                aQ[h][c][0] = sm[base + (m0 + gq)     * RS + 8 * c + tq];
                aQ[h][c][1] = sm[base + (m0 + 8 + gq) * RS + 8 * c + tq];
                aQ[h][c][2] = sm[base + (m0 + gq)     * RS + 8 * c + tq + 4];
                aQ[h][c][3] = sm[base + (m0 + 8 + gq) * RS + 8 * c + tq + 4];
            }
        }

        float oacc[8][4];
#pragma unroll
        for (int n = 0; n < 8; ++n)
#pragma unroll
            for (int k = 0; k < 4; ++k) oacc[n][k] = 0.0f;
        float lA = 0.0f, lB = 0.0f;

        const int qrow0 = t * 64 + m0 + gq;
        const int qrow1 = qrow0 + 8;

#pragma unroll 1
        for (int j = j0; j < j1; ++j) {
            const int kb = j << 6;
            __syncthreads();   // previous iter's mma reads of K/V done

            // ---- stage K [c][d-pairs] and V^T [e][s-pairs] (pure copies) ----
            const uint2* Kh2 = (const uint2*)(g_Kh + ((size_t)b * S_LEN + kb) * 32);
            const uint2* Kl2 = (const uint2*)(g_Kl + ((size_t)b * S_LEN + kb) * 32);
            const uint2* Vh2 = (const uint2*)(g_Vh + (size_t)b * 64 * 2048 + (kb >> 1));
            const uint2* Vl2 = (const uint2*)(g_Vl + (size_t)b * 64 * 2048 + (kb >> 1));
#pragma unroll
            for (int s = 0; s < 8; ++s) {
                int idx = tid + s * 128;        // 0..1023 uint2
                int r   = idx >> 4;             // kv row (K) / e row (V)
                int p2  = idx & 15;
                *(uint2*)&sm[KH_OFF + r * RS + 2 * p2] = Kh2[idx];
                *(uint2*)&sm[KL_OFF + r * RS + 2 * p2] = Kl2[idx];
                *(uint2*)&sm[VH_OFF + r * RS + 2 * p2] = Vh2[r * 1024 + p2];
                *(uint2*)&sm[VL_OFF + r * RS + 2 * p2] = Vl2[r * 1024 + p2];
            }
            __syncthreads();

            // ---- S = Q K^T (3-pass split) ----
            float sacc[8][4];
#pragma unroll
            for (int n = 0; n < 8; ++n)
#pragma unroll
                for (int k = 0; k < 4; ++k) sacc[n][k] = 0.0f;

#pragma unroll
            for (int c = 0; c < 4; ++c) {
#pragma unroll
                for (int n = 0; n < 8; ++n) {
                    int rb = (n * 8 + gq) * RS + 8 * c + tq;
                    uint32_t bh0 = sm[KH_OFF + rb], bh1 = sm[KH_OFF + rb + 4];
                    MMA(sacc[n], aQ[0][c], bh0, bh1);
                    MMA(sacc[n], aQ[1][c], bh0, bh1);
                    uint32_t bl0 = sm[KL_OFF + rb], bl1 = sm[KL_OFF + rb + 4];
                    MMA(sacc[n], aQ[0][c], bl0, bl1);
                }
            }

            // ---- P = exp2(S) with causal mask; accumulate l ----
            const bool dm = (j >= jmask);
#pragma unroll
            for (int n = 0; n < 8; ++n) {
                int col0 = kb + n * 8 + 2 * tq;
                float e0 = ex2(sacc[n][0]);
                float e1 = ex2(sacc[n][1]);
                float e2 = ex2(sacc[n][2]);
                float e3 = ex2(sacc[n][3]);
                if (dm) {
                    e0 = (col0     <= qrow0) ? e0 : 0.0f;
                    e1 = (col0 + 1 <= qrow0) ? e1 : 0.0f;
                    e2 = (col0     <= qrow1) ? e2 : 0.0f;
                    e3 = (col0 + 1 <= qrow1) ? e3 : 0.0f;
                }
                lA += e0 + e1;
                lB += e2 + e3;
                sacc[n][0] = e0; sacc[n][1] = e1;
                sacc[n][2] = e2; sacc[n][3] = e3;
            }

            // ---- P fragments (hi/lo) straight from S fragments ----
            uint32_t aP[2][4][4];
#pragma unroll
            for (int c = 0; c < 4; ++c) {
                split2(sacc[2 * c][0],     sacc[2 * c][1],     aP[0][c][0], aP[1][c][0]);
                split2(sacc[2 * c][2],     sacc[2 * c][3],     aP[0][c][1], aP[1][c][1]);
                split2(sacc[2 * c + 1][0], sacc[2 * c + 1][1], aP[0][c][2], aP[1][c][2]);
                split2(sacc[2 * c + 1][2], sacc[2 * c + 1][3], aP[0][c][3], aP[1][c][3]);
            }

            // ---- O += P V (3-pass split) ----
#pragma unroll
            for (int c = 0; c < 4; ++c) {
#pragma unroll
                for (int n = 0; n < 8; ++n) {
                    int rb = (n * 8 + gq) * RS + 8 * c + tq;
                    uint32_t bh0 = sm[VH_OFF + rb], bh1 = sm[VH_OFF + rb + 4];
                    MMA(oacc[n], aP[0][c], bh0, bh1);
                    MMA(oacc[n], aP[1][c], bh0, bh1);
                    uint32_t bl0 = sm[VL_OFF + rb], bl1 = sm[VL_OFF + rb + 4];
                    MMA(oacc[n], aP[0][c], bl0, bl1);
                }
            }
        }

        // ---- epilogue: write partial O (unnormalized) + l ----
        lA += __shfl_xor_sync(0xffffffffu, lA, 1);
        lA += __shfl_xor_sync(0xffffffffu, lA, 2);
        lB += __shfl_xor_sync(0xffffffffu, lB, 1);
        lB += __shfl_xor_sync(0xffffffffu, lB, 2);

        const int slot = (b * 64 + t) * 2 + part;
        if (tq == 0) {
            g_lpart[(size_t)slot * 64 + m0 + gq]     = lA;
            g_lpart[(size_t)slot * 64 + m0 + 8 + gq] = lB;
        }
        float* Od = g_Opart + (size_t)slot * 64 * 64;
#pragma unroll
        for (int n = 0; n < 8; ++n) {
            int e = n * 8 + 2 * tq;
            *(float2*)(Od + (size_t)(m0 + gq)     * 64 + e) = make_float2(oacc[n][0], oacc[n][1]);
            *(float2*)(Od + (size_t)(m0 + 8 + gq) * 64 + e) = make_float2(oacc[n][2], oacc[n][3]);
        }
        __syncthreads();   // before next seg rewrites Qs
    }
}

// ---------------------------------------------------------------------------
// Combine: out = (O0 [+ O1]) / (l0 [+ l1]); tiles 0..31 one part, 32..63 two.
// ---------------------------------------------------------------------------
__global__ __launch_bounds__(64) void combine_kernel(float* __restrict__ out)
{
    const int bt = blockIdx.x;        // b*64 + t
    const int t  = bt & 63;
    const int r  = threadIdx.x;       // 0..63
    const float* O0 = g_Opart + (((size_t)bt * 2 + 0) * 64 + r) * 64;
    float l = g_lpart[((size_t)bt * 2 + 0) * 64 + r];
    float* o = out + ((size_t)bt * 64 + r) * 64;

    if (t < 32) {
        float inv = __fdividef(1.0f, l);
#pragma unroll
        for (int k = 0; k < 16; ++k) {
            float4 v = *(const float4*)(O0 + 4 * k);
            v.x *= inv; v.y *= inv; v.z *= inv; v.w *= inv;
            *(float4*)(o + 4 * k) = v;
        }
    } else {
        const float* O1 = g_Opart + (((size_t)bt * 2 + 1) * 64 + r) * 64;
        float inv = __fdividef(1.0f, l + g_lpart[((size_t)bt * 2 + 1) * 64 + r]);
#pragma unroll
        for (int k = 0; k < 16; ++k) {
            float4 a = *(const float4*)(O0 + 4 * k);
            float4 c = *(const float4*)(O1 + 4 * k);
            float4 v = make_float4((a.x + c.x) * inv, (a.y + c.y) * inv,
                                   (a.z + c.z) * inv, (a.w + c.w) * inv);
            *(float4*)(o + 4 * k) = v;
        }
    }
}

extern "C" void kernel_launch(void* const* d_in, const int* in_sizes, int n_in,
                              void* d_out, int out_size)
{
    (void)in_sizes; (void)n_in; (void)out_size;
    const float* key_in   = (const float*)d_in[0];
    const float* value_in = (const float*)d_in[1];
    const float* query_in = (const float*)d_in[2];
    const float* Wq       = (const float*)d_in[3];
    const float* Wk       = (const float*)d_in[4];
    const float* Wv       = (const float*)d_in[5];
    float* out = (float*)d_out;

    static int inited = 0;
    if (!inited) {
        cudaFuncSetAttribute(proj_kernel,
                             cudaFuncAttributeMaxDynamicSharedMemorySize,
                             PSM_U32 * sizeof(uint32_t));
        cudaFuncSetAttribute(attn_kernel,
                             cudaFuncAttributeMaxDynamicSharedMemorySize,
                             SMEM_U32 * sizeof(uint32_t));
        inited = 1;
    }

    prep_kernel<<<192, 256>>>(Wq, Wk, Wv);

    dim3 pgrid(NB * S_LEN / 128, 3);  // (128, 3)
    proj_kernel<<<pgrid, 256, PSM_U32 * sizeof(uint32_t)>>>(
        key_in, value_in, query_in);

    dim3 agrid(64, NB);               // 256 balanced CTAs of 128 threads
    attn_kernel<<<agrid, 128, SMEM_U32 * sizeof(uint32_t)>>>();

    combine_kernel<<<NB * 64, 64>>>(out);
}